// round 2
// baseline (speedup 1.0000x reference)
#include <cuda_runtime.h>

#define NH 16
#define SLEN 1024
#define HD 64
#define MROWS 4096              // B*S
#define QROWS 65536             // B*NH*S
#define RREL 257

__device__ float g_Q[QROWS * HD];
__device__ float g_K[QROWS * HD];
__device__ float g_V[QROWS * HD];
__device__ float g_QE[QROWS * RREL];
__device__ float g_AO[MROWS * 1024];

// C = A@W^T + bias. A:[M,K], W:[N,K] row-major. mode0: C[m*N+n]. mode1: QKV layout.
__global__ __launch_bounds__(256) void gemm64(
    const float* __restrict__ A, const float* __restrict__ W,
    const float* __restrict__ bias, float* __restrict__ C,
    int M, int N, int K, int mode)
{
    __shared__ __align__(16) float As[32 * 68];
    __shared__ __align__(16) float Bs[32 * 68];
    const int tid = threadIdx.x, tx = tid & 15, ty = tid >> 4;
    const int m0 = blockIdx.y << 6, n0 = blockIdx.x << 6;
    float acc[4][4] = {};
    for (int k0 = 0; k0 < K; k0 += 32) {
#pragma unroll
        for (int it = 0; it < 2; ++it) {
            int f = tid + (it << 8), row = f >> 3, c4 = (f & 7) << 2;
            float4 va = *reinterpret_cast<const float4*>(A + (size_t)(m0 + row) * K + k0 + c4);
            As[(c4+0)*68+row]=va.x; As[(c4+1)*68+row]=va.y; As[(c4+2)*68+row]=va.z; As[(c4+3)*68+row]=va.w;
            float4 vw = make_float4(0.f,0.f,0.f,0.f);
            if (n0 + row < N)
                vw = *reinterpret_cast<const float4*>(W + (size_t)(n0 + row) * K + k0 + c4);
            Bs[(c4+0)*68+row]=vw.x; Bs[(c4+1)*68+row]=vw.y; Bs[(c4+2)*68+row]=vw.z; Bs[(c4+3)*68+row]=vw.w;
        }
        __syncthreads();
#pragma unroll 8
        for (int k = 0; k < 32; ++k) {
            float4 a = *reinterpret_cast<const float4*>(As + k*68 + (ty<<2));
            float4 b = *reinterpret_cast<const float4*>(Bs + k*68 + (tx<<2));
            float av[4] = {a.x,a.y,a.z,a.w}, bv[4] = {b.x,b.y,b.z,b.w};
#pragma unroll
            for (int i = 0; i < 4; ++i)
#pragma unroll
                for (int j = 0; j < 4; ++j) acc[i][j] = fmaf(av[i], bv[j], acc[i][j]);
        }
        __syncthreads();
    }
#pragma unroll
    for (int i = 0; i < 4; ++i) {
        const int m = m0 + (ty << 2) + i;
#pragma unroll
        for (int j = 0; j < 4; ++j) {
            const int n = n0 + (tx << 2) + j;
            if (n >= N) continue;
            float v = acc[i][j] + (bias ? bias[n] : 0.f);
            if (mode == 0) C[(size_t)m * N + n] = v;
            else {
                int b = m >> 10, s = m & 1023, h = n >> 6, d = n & 63;
                C[(((size_t)(b * NH + h)) * SLEN + s) * HD + d] = v;
            }
        }
    }
}

// Flash attention w/ rel-pos bias gather. grid(64 bh, 16 qtiles), 256 thr.
__global__ __launch_bounds__(256) void flash64(
    const float* __restrict__ Q, const float* __restrict__ K,
    const float* __restrict__ V, const float* __restrict__ QE,
    float* __restrict__ O)
{
    extern __shared__ __align__(16) float sm[];
    float* Qs = sm;                // [64][68] d-major
    float* Ks = sm + 64*68;        // [64][68] d-major
    float* Vs = sm + 2*64*68;      // [64][68] k-major
    float* Ps = sm + 3*64*68;      // [64][68]
    const int tid = threadIdx.x, tx = tid & 15, ty = tid >> 4;
    const int bh = blockIdx.x, q0 = blockIdx.y << 6;
    const float* Qb = Q + ((size_t)bh * SLEN + q0) * HD;
    const float* Kb = K + (size_t)bh * SLEN * HD;
    const float* Vb = V + (size_t)bh * SLEN * HD;
    const float* QEb = QE + ((size_t)bh * SLEN + q0) * RREL;
#pragma unroll
    for (int it = 0; it < 4; ++it) {
        int f = tid + (it << 8), row = f >> 4, c4 = (f & 15) << 2;
        float4 v = *reinterpret_cast<const float4*>(Qb + (size_t)row * HD + c4);
        Qs[(c4+0)*68+row]=v.x; Qs[(c4+1)*68+row]=v.y; Qs[(c4+2)*68+row]=v.z; Qs[(c4+3)*68+row]=v.w;
    }
    float m_[4], l_[4] = {}, o_[4][4] = {};
#pragma unroll
    for (int i = 0; i < 4; ++i) m_[i] = -1e30f;

    for (int kt = 0; kt < 16; ++kt) {
        const int k0 = kt << 6;
        __syncthreads();
#pragma unroll
        for (int it = 0; it < 4; ++it) {
            int f = tid + (it << 8), row = f >> 4, c4 = (f & 15) << 2;
            float4 v = *reinterpret_cast<const float4*>(Kb + (size_t)(k0 + row) * HD + c4);
            Ks[(c4+0)*68+row]=v.x; Ks[(c4+1)*68+row]=v.y; Ks[(c4+2)*68+row]=v.z; Ks[(c4+3)*68+row]=v.w;
            float4 w = *reinterpret_cast<const float4*>(Vb + (size_t)(k0 + row) * HD + c4);
            *reinterpret_cast<float4*>(Vs + row*68 + c4) = w;
        }
        __syncthreads();
        float s_[4][4] = {};
#pragma unroll 8
        for (int d = 0; d < 64; ++d) {
            float4 a = *reinterpret_cast<const float4*>(Qs + d*68 + (ty<<2));
            float4 b = *reinterpret_cast<const float4*>(Ks + d*68 + (tx<<2));
            float av[4] = {a.x,a.y,a.z,a.w}, bv[4] = {b.x,b.y,b.z,b.w};
#pragma unroll
            for (int i = 0; i < 4; ++i)
#pragma unroll
                for (int j = 0; j < 4; ++j) s_[i][j] = fmaf(av[i], bv[j], s_[i][j]);
        }
#pragma unroll
        for (int i = 0; i < 4; ++i) {
            const int qg = q0 + (ty << 2) + i;
            const float* QEr = QEb + (size_t)((ty << 2) + i) * RREL;
            float mt = -1e30f;
#pragma unroll
            for (int j = 0; j < 4; ++j) {
                int rel = k0 + (tx << 2) + j - qg;
                rel = rel < -128 ? -128 : (rel > 128 ? 128 : rel);
                float sv = (s_[i][j] + __ldg(QEr + rel + 128)) * 0.125f;
                s_[i][j] = sv; mt = fmaxf(mt, sv);
            }
            mt = fmaxf(mt, __shfl_xor_sync(~0u, mt, 8));
            mt = fmaxf(mt, __shfl_xor_sync(~0u, mt, 4));
            mt = fmaxf(mt, __shfl_xor_sync(~0u, mt, 2));
            mt = fmaxf(mt, __shfl_xor_sync(~0u, mt, 1));
            float mnew = fmaxf(m_[i], mt);
            float alpha = __expf(m_[i] - mnew), rs = 0.f;
#pragma unroll
            for (int j = 0; j < 4; ++j) { float p = __expf(s_[i][j] - mnew); s_[i][j] = p; rs += p; }
            rs += __shfl_xor_sync(~0u, rs, 8);
            rs += __shfl_xor_sync(~0u, rs, 4);
            rs += __shfl_xor_sync(~0u, rs, 2);
            rs += __shfl_xor_sync(~0u, rs, 1);
            l_[i] = l_[i] * alpha + rs; m_[i] = mnew;
#pragma unroll
            for (int j = 0; j < 4; ++j) o_[i][j] *= alpha;
            *reinterpret_cast<float4*>(Ps + ((ty<<2)+i)*68 + (tx<<2)) =
                make_float4(s_[i][0], s_[i][1], s_[i][2], s_[i][3]);
        }
        __syncthreads();
#pragma unroll 8
        for (int kk = 0; kk < 64; ++kk) {
            float a0 = Ps[((ty<<2)+0)*68+kk], a1 = Ps[((ty<<2)+1)*68+kk];
            float a2 = Ps[((ty<<2)+2)*68+kk], a3 = Ps[((ty<<2)+3)*68+kk];
            float4 b = *reinterpret_cast<const float4*>(Vs + kk*68 + (tx<<2));
            o_[0][0]=fmaf(a0,b.x,o_[0][0]); o_[0][1]=fmaf(a0,b.y,o_[0][1]);
            o_[0][2]=fmaf(a0,b.z,o_[0][2]); o_[0][3]=fmaf(a0,b.w,o_[0][3]);
            o_[1][0]=fmaf(a1,b.x,o_[1][0]); o_[1][1]=fmaf(a1,b.y,o_[1][1]);
            o_[1][2]=fmaf(a1,b.z,o_[1][2]); o_[1][3]=fmaf(a1,b.w,o_[1][3]);
            o_[2][0]=fmaf(a2,b.x,o_[2][0]); o_[2][1]=fmaf(a2,b.y,o_[2][1]);
            o_[2][2]=fmaf(a2,b.z,o_[2][2]); o_[2][3]=fmaf(a2,b.w,o_[2][3]);
            o_[3][0]=fmaf(a3,b.x,o_[3][0]); o_[3][1]=fmaf(a3,b.y,o_[3][1]);
            o_[3][2]=fmaf(a3,b.z,o_[3][2]); o_[3][3]=fmaf(a3,b.w,o_[3][3]);
        }
    }
    const int b = bh >> 4, h = bh & 15;
#pragma unroll
    for (int i = 0; i < 4; ++i) {
        const int q = q0 + (ty << 2) + i;
        const float inv = 1.f / l_[i];
        *reinterpret_cast<float4*>(g_AO + ((size_t)(b*1024+q))*1024 + h*64 + (tx<<2)) =
            make_float4(o_[i][0]*inv, o_[i][1]*inv, o_[i][2]*inv, o_[i][3]*inv);
    }
    (void)O;
}

extern "C" void kernel_launch(void* const* d_in, const int* in_sizes, int n_in,
                              void* d_out, int out_size) {
    const float* x   = (const float*)d_in[0];
    const float* Wq  = (const float*)d_in[1];
    const float* bq  = (const float*)d_in[2];
    const float* Wk  = (const float*)d_in[3];
    const float* bk  = (const float*)d_in[4];
    const float* Wv  = (const float*)d_in[5];
    const float* bv  = (const float*)d_in[6];
    const float* Wo  = (const float*)d_in[7];
    const float* bo  = (const float*)d_in[8];
    const float* rel = (const float*)d_in[9];
    float* out = (float*)d_out;

    float *Qp, *Kp, *Vp, *QEp, *AOp;
    cudaGetSymbolAddress((void**)&Qp,  g_Q);
    cudaGetSymbolAddress((void**)&Kp,  g_K);
    cudaGetSymbolAddress((void**)&Vp,  g_V);
    cudaGetSymbolAddress((void**)&QEp, g_QE);
    cudaGetSymbolAddress((void**)&AOp, g_AO);

    dim3 gproj(16, 64);            // N=1024/64, M=4096/64
    gemm64<<<gproj, 256>>>(x, Wq, bq, Qp, MROWS, 1024, 1024, 1);
    gemm64<<<gproj, 256>>>(x, Wk, bk, Kp, MROWS, 1024, 1024, 1);
    gemm64<<<gproj, 256>>>(x, Wv, bv, Vp, MROWS, 1024, 1024, 1);
    // QE = Q @ rel^T : [65536,64] x [257,64]^T
    gemm64<<<dim3(5, 1024), 256>>>(Qp, rel, nullptr, QEp, QROWS, RREL, HD, 0);

    static int smset = 0;
    const int smem = 4 * 64 * 68 * (int)sizeof(float);
    if (!smset) { cudaFuncSetAttribute(flash64, cudaFuncAttributeMaxDynamicSharedMemorySize, smem); smset = 1; }
    flash64<<<dim3(64, 16), 256, smem>>>(Qp, Kp, Vp, QEp, nullptr);

    gemm64<<<gproj, 256>>>(AOp, Wo, bo, out, MROWS, 1024, 1024, 0);
    (void)in_sizes; (void)n_in; (void)out_size;
}

// round 4
// speedup vs baseline: 1.8819x; 1.8819x over previous
#include <cuda_runtime.h>
#include <cuda_bf16.h>
#include <cstdint>

#define NH 16
#define SLEN 1024
#define HD 64
#define MROWS 4096
#define QROWS 65536
#define RREL 257

__device__ float g_Q[QROWS * HD];
__device__ float g_K[QROWS * HD];
__device__ float g_V[QROWS * HD];
__device__ float g_QE[QROWS * RREL];
__device__ float g_AO[MROWS * 1024];
__device__ __nv_bfloat16 g_xhi[MROWS * 1024], g_xlo[MROWS * 1024];
__device__ __nv_bfloat16 g_whi[4 * 1024 * 1024], g_wlo[4 * 1024 * 1024];
__device__ __nv_bfloat16 g_aohi[MROWS * 1024], g_aolo[MROWS * 1024];

__device__ __forceinline__ uint32_t smem_u32(const void* p) {
    uint32_t a;
    asm("{ .reg .u64 t; cvta.to.shared.u64 t, %1; cvt.u32.u64 %0, t; }" : "=r"(a) : "l"(p));
    return a;
}
__device__ __forceinline__ uint32_t swz128(uint32_t b) { return b ^ ((b >> 3) & 0x70); }
__device__ __forceinline__ void ldsm4(uint32_t* r, uint32_t a) {
    asm volatile("ldmatrix.sync.aligned.m8n8.x4.shared.b16 {%0,%1,%2,%3}, [%4];"
                 : "=r"(r[0]), "=r"(r[1]), "=r"(r[2]), "=r"(r[3]) : "r"(a));
}
__device__ __forceinline__ void mma16816(float* c, const uint32_t* a, const uint32_t* b) {
    asm volatile(
        "mma.sync.aligned.m16n8k16.row.col.f32.bf16.bf16.f32 "
        "{%0,%1,%2,%3},{%4,%5,%6,%7},{%8,%9},{%0,%1,%2,%3};"
        : "+f"(c[0]), "+f"(c[1]), "+f"(c[2]), "+f"(c[3])
        : "r"(a[0]), "r"(a[1]), "r"(a[2]), "r"(a[3]), "r"(b[0]), "r"(b[1]));
}
__device__ __forceinline__ void cpasync16(uint32_t sa, const void* ga) {
    asm volatile("cp.async.cg.shared.global [%0], [%1], 16;" :: "r"(sa), "l"(ga));
}
#define CP_COMMIT() asm volatile("cp.async.commit_group;" ::: "memory")
#define CP_WAIT1()  asm volatile("cp.async.wait_group 1;" ::: "memory")
#define CP_WAIT0()  asm volatile("cp.async.wait_group 0;" ::: "memory")

__global__ void splitk(const float* __restrict__ s, __nv_bfloat16* __restrict__ hi,
                       __nv_bfloat16* __restrict__ lo, int n) {
    int i = blockIdx.x * blockDim.x + threadIdx.x;
    if (i < n) {
        float v = s[i];
        __nv_bfloat16 h = __float2bfloat16(v);
        hi[i] = h;
        lo[i] = __float2bfloat16(v - __bfloat162float(h));
    }
}

// C = (Ahi+Alo) @ (Bhi+Blo)^T + bias, via mma.sync bf16 3-term split.
// A*:[M,K] bf16 K-major, B*:[N,K] bf16 K-major. CTA tile 128x128, K chunk 64.
__global__ __launch_bounds__(256) void gemm_mma(
    const __nv_bfloat16* __restrict__ Ahi, const __nv_bfloat16* __restrict__ Alo,
    const __nv_bfloat16* __restrict__ Bhi, const __nv_bfloat16* __restrict__ Blo,
    const float* __restrict__ bias, float* __restrict__ C, int K, int N, int mode)
{
    extern __shared__ char dsm[];
    const uint32_t sbase = (smem_u32(dsm) + 1023u) & ~1023u;
    const int tid = threadIdx.x, wid = tid >> 5, lane = tid & 31;
    const int warp_m = wid & 3, warp_n = wid >> 2;
    const int m0 = blockIdx.y << 7, n0 = blockIdx.x << 7;
    const __nv_bfloat16* srcs[4] = {
        Ahi + (size_t)m0 * K, Alo + (size_t)m0 * K,
        Bhi + (size_t)n0 * K, Blo + (size_t)n0 * K };
    const int nch = K >> 6;

    // per-thread load pattern: 16 x 16B per chunk (4 parts x 128 rows x 8 segs)
    auto load_chunk = [&](int c) {
        const uint32_t bb = sbase + ((c & 1) << 16);
        const int k0 = c << 6;
#pragma unroll
        for (int it = 0; it < 16; ++it) {
            int f = (it << 8) + tid;
            int p = f >> 10, q = f & 1023, r = q >> 3, g = q & 7;
            cpasync16(bb + (p << 14) + swz128((r << 7) + (g << 4)),
                      srcs[p] + (size_t)r * K + k0 + (g << 3));
        }
        CP_COMMIT();
    };

    float acc[2][8][4] = {};
    load_chunk(0);

    for (int c = 0; c < nch; ++c) {
        if (c + 1 < nch) { load_chunk(c + 1); CP_WAIT1(); }
        else             { CP_WAIT0(); }
        __syncthreads();
        const uint32_t bb = sbase + ((c & 1) << 16);
        const uint32_t pAh = bb, pAl = bb + 16384, pBh = bb + 32768, pBl = bb + 49152;
#pragma unroll
        for (int s = 0; s < 4; ++s) {
            uint32_t aH[2][4], aL[2][4];
#pragma unroll
            for (int mb = 0; mb < 2; ++mb) {
                int row = (warp_m << 5) + (mb << 4) + (lane & 15);
                int kseg = (s << 1) + (lane >> 4);
                uint32_t off = swz128((row << 7) + (kseg << 4));
                ldsm4(aH[mb], pAh + off);
                ldsm4(aL[mb], pAl + off);
            }
#pragma unroll
            for (int nbp = 0; nbp < 4; ++nbp) {
                int nrow = (warp_n << 6) + (nbp << 4) + (lane & 7) + ((lane >> 4) << 3);
                int kseg = (s << 1) + ((lane >> 3) & 1);
                uint32_t off = swz128((nrow << 7) + (kseg << 4));
                uint32_t bH[4], bL[4];
                ldsm4(bH, pBh + off);
                ldsm4(bL, pBl + off);
#pragma unroll
                for (int mb = 0; mb < 2; ++mb) {
#pragma unroll
                    for (int j = 0; j < 2; ++j) {
                        float* cc = acc[mb][(nbp << 1) + j];
                        mma16816(cc, aH[mb], bH + (j << 1));
                        mma16816(cc, aH[mb], bL + (j << 1));
                        mma16816(cc, aL[mb], bH + (j << 1));
                    }
                }
            }
        }
        __syncthreads();
    }

    // epilogue
#pragma unroll
    for (int mb = 0; mb < 2; ++mb) {
        const int rbase = m0 + (warp_m << 5) + (mb << 4) + (lane >> 2);
#pragma unroll
        for (int nb = 0; nb < 8; ++nb) {
            const int col = n0 + (warp_n << 6) + (nb << 3) + ((lane & 3) << 1);
            const float b0 = bias[col], b1 = bias[col + 1];
#pragma unroll
            for (int half = 0; half < 2; ++half) {
                const int row = rbase + (half << 3);
                float2 v = make_float2(acc[mb][nb][(half << 1)] + b0,
                                       acc[mb][nb][(half << 1) + 1] + b1);
                if (mode == 0) {
                    *reinterpret_cast<float2*>(C + (size_t)row * N + col) = v;
                } else {
                    const int bb_ = row >> 10, ss = row & 1023, h = col >> 6, d = col & 63;
                    *reinterpret_cast<float2*>(
                        C + ((((size_t)((bb_ << 4) + h)) << 10) + ss) * 64 + d) = v;
                }
            }
        }
    }
}

// SIMT GEMM (QE): C = A@W^T. A:[M,K] W:[N,K].
__global__ __launch_bounds__(256) void gemm64(
    const float* __restrict__ A, const float* __restrict__ W,
    float* __restrict__ C, int M, int N, int K)
{
    __shared__ __align__(16) float As[32 * 68];
    __shared__ __align__(16) float Bs[32 * 68];
    const int tid = threadIdx.x, tx = tid & 15, ty = tid >> 4;
    const int m0 = blockIdx.y << 6, n0 = blockIdx.x << 6;
    float acc[4][4] = {};
    for (int k0 = 0; k0 < K; k0 += 32) {
#pragma unroll
        for (int it = 0; it < 2; ++it) {
            int f = tid + (it << 8), row = f >> 3, c4 = (f & 7) << 2;
            float4 va = *reinterpret_cast<const float4*>(A + (size_t)(m0 + row) * K + k0 + c4);
            As[(c4+0)*68+row]=va.x; As[(c4+1)*68+row]=va.y; As[(c4+2)*68+row]=va.z; As[(c4+3)*68+row]=va.w;
            float4 vw = make_float4(0.f, 0.f, 0.f, 0.f);
            if (n0 + row < N)
                vw = *reinterpret_cast<const float4*>(W + (size_t)(n0 + row) * K + k0 + c4);
            Bs[(c4+0)*68+row]=vw.x; Bs[(c4+1)*68+row]=vw.y; Bs[(c4+2)*68+row]=vw.z; Bs[(c4+3)*68+row]=vw.w;
        }
        __syncthreads();
#pragma unroll 8
        for (int k = 0; k < 32; ++k) {
            float4 a = *reinterpret_cast<const float4*>(As + k*68 + (ty<<2));
            float4 b = *reinterpret_cast<const float4*>(Bs + k*68 + (tx<<2));
            float av[4] = {a.x,a.y,a.z,a.w}, bv[4] = {b.x,b.y,b.z,b.w};
#pragma unroll
            for (int i = 0; i < 4; ++i)
#pragma unroll
                for (int j = 0; j < 4; ++j) acc[i][j] = fmaf(av[i], bv[j], acc[i][j]);
        }
        __syncthreads();
    }
#pragma unroll
    for (int i = 0; i < 4; ++i) {
        const int m = m0 + (ty << 2) + i;
#pragma unroll
        for (int j = 0; j < 4; ++j) {
            const int n = n0 + (tx << 2) + j;
            if (n < N) C[(size_t)m * N + n] = acc[i][j];
        }
    }
}

// flash attention w/ rel-pos bias (unchanged from R2)
__global__ __launch_bounds__(256) void flash64(
    const float* __restrict__ Q, const float* __restrict__ K,
    const float* __restrict__ V, const float* __restrict__ QE)
{
    extern __shared__ __align__(16) float sm[];
    float* Qs = sm;
    float* Ks = sm + 64*68;
    float* Vs = sm + 2*64*68;
    float* Ps = sm + 3*64*68;
    const int tid = threadIdx.x, tx = tid & 15, ty = tid >> 4;
    const int bh = blockIdx.x, q0 = blockIdx.y << 6;
    const float* Qb = Q + ((size_t)bh * SLEN + q0) * HD;
    const float* Kb = K + (size_t)bh * SLEN * HD;
    const float* Vb = V + (size_t)bh * SLEN * HD;
    const float* QEb = QE + ((size_t)bh * SLEN + q0) * RREL;
#pragma unroll
    for (int it = 0; it < 4; ++it) {
        int f = tid + (it << 8), row = f >> 4, c4 = (f & 15) << 2;
        float4 v = *reinterpret_cast<const float4*>(Qb + (size_t)row * HD + c4);
        Qs[(c4+0)*68+row]=v.x; Qs[(c4+1)*68+row]=v.y; Qs[(c4+2)*68+row]=v.z; Qs[(c4+3)*68+row]=v.w;
    }
    float m_[4], l_[4] = {}, o_[4][4] = {};
#pragma unroll
    for (int i = 0; i < 4; ++i) m_[i] = -1e30f;

    for (int kt = 0; kt < 16; ++kt) {
        const int k0 = kt << 6;
        __syncthreads();
#pragma unroll
        for (int it = 0; it < 4; ++it) {
            int f = tid + (it << 8), row = f >> 4, c4 = (f & 15) << 2;
            float4 v = *reinterpret_cast<const float4*>(Kb + (size_t)(k0 + row) * HD + c4);
            Ks[(c4+0)*68+row]=v.x; Ks[(c4+1)*68+row]=v.y; Ks[(c4+2)*68+row]=v.z; Ks[(c4+3)*68+row]=v.w;
            float4 w = *reinterpret_cast<const float4*>(Vb + (size_t)(k0 + row) * HD + c4);
            *reinterpret_cast<float4*>(Vs + row*68 + c4) = w;
        }
        __syncthreads();
        float s_[4][4] = {};
#pragma unroll 8
        for (int d = 0; d < 64; ++d) {
            float4 a = *reinterpret_cast<const float4*>(Qs + d*68 + (ty<<2));
            float4 b = *reinterpret_cast<const float4*>(Ks + d*68 + (tx<<2));
            float av[4] = {a.x,a.y,a.z,a.w}, bv[4] = {b.x,b.y,b.z,b.w};
#pragma unroll
            for (int i = 0; i < 4; ++i)
#pragma unroll
                for (int j = 0; j < 4; ++j) s_[i][j] = fmaf(av[i], bv[j], s_[i][j]);
        }
#pragma unroll
        for (int i = 0; i < 4; ++i) {
            const int qg = q0 + (ty << 2) + i;
            const float* QEr = QEb + (size_t)((ty << 2) + i) * RREL;
            float mt = -1e30f;
#pragma unroll
            for (int j = 0; j < 4; ++j) {
                int rel = k0 + (tx << 2) + j - qg;
                rel = rel < -128 ? -128 : (rel > 128 ? 128 : rel);
                float sv = (s_[i][j] + __ldg(QEr + rel + 128)) * 0.125f;
                s_[i][j] = sv; mt = fmaxf(mt, sv);
            }
            mt = fmaxf(mt, __shfl_xor_sync(~0u, mt, 8));
            mt = fmaxf(mt, __shfl_xor_sync(~0u, mt, 4));
            mt = fmaxf(mt, __shfl_xor_sync(~0u, mt, 2));
            mt = fmaxf(mt, __shfl_xor_sync(~0u, mt, 1));
            float mnew = fmaxf(m_[i], mt);
            float alpha = __expf(m_[i] - mnew), rs = 0.f;
#pragma unroll
            for (int j = 0; j < 4; ++j) { float p = __expf(s_[i][j] - mnew); s_[i][j] = p; rs += p; }
            rs += __shfl_xor_sync(~0u, rs, 8);
            rs += __shfl_xor_sync(~0u, rs, 4);
            rs += __shfl_xor_sync(~0u, rs, 2);
            rs += __shfl_xor_sync(~0u, rs, 1);
            l_[i] = l_[i] * alpha + rs; m_[i] = mnew;
#pragma unroll
            for (int j = 0; j < 4; ++j) o_[i][j] *= alpha;
            *reinterpret_cast<float4*>(Ps + ((ty<<2)+i)*68 + (tx<<2)) =
                make_float4(s_[i][0], s_[i][1], s_[i][2], s_[i][3]);
        }
        __syncthreads();
#pragma unroll 8
        for (int kk = 0; kk < 64; ++kk) {
            float a0 = Ps[((ty<<2)+0)*68+kk], a1 = Ps[((ty<<2)+1)*68+kk];
            float a2 = Ps[((ty<<2)+2)*68+kk], a3 = Ps[((ty<<2)+3)*68+kk];
            float4 b = *reinterpret_cast<const float4*>(Vs + kk*68 + (tx<<2));
            o_[0][0]=fmaf(a0,b.x,o_[0][0]); o_[0][1]=fmaf(a0,b.y,o_[0][1]);
            o_[0][2]=fmaf(a0,b.z,o_[0][2]); o_[0][3]=fmaf(a0,b.w,o_[0][3]);
            o_[1][0]=fmaf(a1,b.x,o_[1][0]); o_[1][1]=fmaf(a1,b.y,o_[1][1]);
            o_[1][2]=fmaf(a1,b.z,o_[1][2]); o_[1][3]=fmaf(a1,b.w,o_[1][3]);
            o_[2][0]=fmaf(a2,b.x,o_[2][0]); o_[2][1]=fmaf(a2,b.y,o_[2][1]);
            o_[2][2]=fmaf(a2,b.z,o_[2][2]); o_[2][3]=fmaf(a2,b.w,o_[2][3]);
            o_[3][0]=fmaf(a3,b.x,o_[3][0]); o_[3][1]=fmaf(a3,b.y,o_[3][1]);
            o_[3][2]=fmaf(a3,b.z,o_[3][2]); o_[3][3]=fmaf(a3,b.w,o_[3][3]);
        }
    }
    const int b = bh >> 4, h = bh & 15;
#pragma unroll
    for (int i = 0; i < 4; ++i) {
        const int q = q0 + (ty << 2) + i;
        const float inv = 1.f / l_[i];
        *reinterpret_cast<float4*>(g_AO + ((size_t)(b*1024+q))*1024 + h*64 + (tx<<2)) =
            make_float4(o_[i][0]*inv, o_[i][1]*inv, o_[i][2]*inv, o_[i][3]*inv);
    }
}

extern "C" void kernel_launch(void* const* d_in, const int* in_sizes, int n_in,
                              void* d_out, int out_size) {
    const float* x   = (const float*)d_in[0];
    const float* Wq  = (const float*)d_in[1];
    const float* bq  = (const float*)d_in[2];
    const float* Wk  = (const float*)d_in[3];
    const float* bk  = (const float*)d_in[4];
    const float* Wv  = (const float*)d_in[5];
    const float* bv  = (const float*)d_in[6];
    const float* Wo  = (const float*)d_in[7];
    const float* bo  = (const float*)d_in[8];
    const float* rel = (const float*)d_in[9];
    float* out = (float*)d_out;

    float *Qp, *Kp, *Vp, *QEp, *AOp;
    cudaGetSymbolAddress((void**)&Qp,  g_Q);
    cudaGetSymbolAddress((void**)&Kp,  g_K);
    cudaGetSymbolAddress((void**)&Vp,  g_V);
    cudaGetSymbolAddress((void**)&QEp, g_QE);
    cudaGetSymbolAddress((void**)&AOp, g_AO);
    __nv_bfloat16 *xhi, *xlo, *whi, *wlo, *aohi, *aolo;
    cudaGetSymbolAddress((void**)&xhi, g_xhi);
    cudaGetSymbolAddress((void**)&xlo, g_xlo);
    cudaGetSymbolAddress((void**)&whi, g_whi);
    cudaGetSymbolAddress((void**)&wlo, g_wlo);
    cudaGetSymbolAddress((void**)&aohi, g_aohi);
    cudaGetSymbolAddress((void**)&aolo, g_aolo);

    static int once = 0;
    const int smem_mm = 132096;
    const int smem_fl = 4 * 64 * 68 * (int)sizeof(float);
    if (!once) {
        cudaFuncSetAttribute(gemm_mma, cudaFuncAttributeMaxDynamicSharedMemorySize, smem_mm);
        cudaFuncSetAttribute(flash64, cudaFuncAttributeMaxDynamicSharedMemorySize, smem_fl);
        once = 1;
    }

    const int NW = 1024 * 1024;
    splitk<<<(MROWS * 1024 + 255) / 256, 256>>>(x,  xhi, xlo, MROWS * 1024);
    splitk<<<(NW + 255) / 256, 256>>>(Wq, whi,          wlo,          NW);
    splitk<<<(NW + 255) / 256, 256>>>(Wk, whi + NW,     wlo + NW,     NW);
    splitk<<<(NW + 255) / 256, 256>>>(Wv, whi + 2 * NW, wlo + 2 * NW, NW);
    splitk<<<(NW + 255) / 256, 256>>>(Wo, whi + 3 * NW, wlo + 3 * NW, NW);

    dim3 gmm(8, 32);  // N/128, M/128
    gemm_mma<<<gmm, 256, smem_mm>>>(xhi, xlo, whi,          wlo,          bq, Qp, 1024, 1024, 1);
    gemm_mma<<<gmm, 256, smem_mm>>>(xhi, xlo, whi + NW,     wlo + NW,     bk, Kp, 1024, 1024, 1);
    gemm_mma<<<gmm, 256, smem_mm>>>(xhi, xlo, whi + 2 * NW, wlo + 2 * NW, bv, Vp, 1024, 1024, 1);

    gemm64<<<dim3(5, 1024), 256>>>(Qp, rel, QEp, QROWS, RREL, HD);
    flash64<<<dim3(64, 16), 256, smem_fl>>>(Qp, Kp, Vp, QEp);

    splitk<<<(MROWS * 1024 + 255) / 256, 256>>>(AOp, aohi, aolo, MROWS * 1024);
    gemm_mma<<<gmm, 256, smem_mm>>>(aohi, aolo, whi + 3 * NW, wlo + 3 * NW, bo, out, 1024, 1024, 0);

    (void)in_sizes; (void)n_in; (void)out_size;
}

// round 5
// speedup vs baseline: 2.7209x; 1.4458x over previous
#include <cuda_runtime.h>
#include <cuda_bf16.h>
#include <cuda_fp16.h>
#include <cstdint>

#define NH 16
#define MROWS 4096
#define QROWS 65536
#define RREL 257

__device__ float g_QE[(size_t)QROWS * RREL];
__device__ float g_AO[MROWS * 1024];
__device__ __half g_Qh[QROWS * 64], g_Kh[QROWS * 64], g_Vh[QROWS * 64];
__device__ __nv_bfloat16 g_xhi[MROWS * 1024], g_xlo[MROWS * 1024];
__device__ __nv_bfloat16 g_whi[4 * 1024 * 1024], g_wlo[4 * 1024 * 1024];
__device__ __nv_bfloat16 g_aohi[MROWS * 1024], g_aolo[MROWS * 1024];

__device__ __forceinline__ uint32_t smem_u32(const void* p) {
    uint32_t a;
    asm("{ .reg .u64 t; cvta.to.shared.u64 t, %1; cvt.u32.u64 %0, t; }" : "=r"(a) : "l"(p));
    return a;
}
__device__ __forceinline__ uint32_t swz128(uint32_t b) { return b ^ ((b >> 3) & 0x70); }
__device__ __forceinline__ void ldsm4(uint32_t* r, uint32_t a) {
    asm volatile("ldmatrix.sync.aligned.m8n8.x4.shared.b16 {%0,%1,%2,%3}, [%4];"
                 : "=r"(r[0]), "=r"(r[1]), "=r"(r[2]), "=r"(r[3]) : "r"(a));
}
__device__ __forceinline__ void ldsm4t(uint32_t* r, uint32_t a) {
    asm volatile("ldmatrix.sync.aligned.m8n8.x4.trans.shared.b16 {%0,%1,%2,%3}, [%4];"
                 : "=r"(r[0]), "=r"(r[1]), "=r"(r[2]), "=r"(r[3]) : "r"(a));
}
__device__ __forceinline__ void mma16816(float* c, const uint32_t* a, const uint32_t* b) {
    asm volatile(
        "mma.sync.aligned.m16n8k16.row.col.f32.bf16.bf16.f32 "
        "{%0,%1,%2,%3},{%4,%5,%6,%7},{%8,%9},{%0,%1,%2,%3};"
        : "+f"(c[0]), "+f"(c[1]), "+f"(c[2]), "+f"(c[3])
        : "r"(a[0]), "r"(a[1]), "r"(a[2]), "r"(a[3]), "r"(b[0]), "r"(b[1]));
}
__device__ __forceinline__ void mma16816h(float* c, const uint32_t* a, const uint32_t* b) {
    asm volatile(
        "mma.sync.aligned.m16n8k16.row.col.f32.f16.f16.f32 "
        "{%0,%1,%2,%3},{%4,%5,%6,%7},{%8,%9},{%0,%1,%2,%3};"
        : "+f"(c[0]), "+f"(c[1]), "+f"(c[2]), "+f"(c[3])
        : "r"(a[0]), "r"(a[1]), "r"(a[2]), "r"(a[3]), "r"(b[0]), "r"(b[1]));
}
__device__ __forceinline__ void cpasync16(uint32_t sa, const void* ga) {
    asm volatile("cp.async.cg.shared.global [%0], [%1], 16;" :: "r"(sa), "l"(ga));
}
#define CP_COMMIT() asm volatile("cp.async.commit_group;" ::: "memory")
#define CP_WAIT1()  asm volatile("cp.async.wait_group 1;" ::: "memory")
#define CP_WAIT0()  asm volatile("cp.async.wait_group 0;" ::: "memory")
#define STS128(a, v) asm volatile("st.shared.v4.b32 [%0], {%1,%2,%3,%4};" \
    :: "r"(a), "r"(v.x), "r"(v.y), "r"(v.z), "r"(v.w) : "memory")

__global__ void splitk(const float* __restrict__ s, __nv_bfloat16* __restrict__ hi,
                       __nv_bfloat16* __restrict__ lo, int n) {
    int i = blockIdx.x * blockDim.x + threadIdx.x;
    if (i < n) {
        float v = s[i];
        __nv_bfloat16 h = __float2bfloat16(v);
        hi[i] = h;
        lo[i] = __float2bfloat16(v - __bfloat162float(h));
    }
}

// C = (Ahi+Alo)@(Bhi+Blo)^T + bias. 3-term bf16 split. Tile 128x128, Kchunk 64.
// mode0: fp32 C[m*N+n]; mode1: fp16 Ch in [b,h,s,d] layout.
__global__ __launch_bounds__(256) void gemm_mma(
    const __nv_bfloat16* __restrict__ Ahi, const __nv_bfloat16* __restrict__ Alo,
    const __nv_bfloat16* __restrict__ Bhi, const __nv_bfloat16* __restrict__ Blo,
    const float* __restrict__ bias, float* __restrict__ C, __half* __restrict__ Ch,
    int K, int N, int mode)
{
    extern __shared__ char dsm[];
    const uint32_t sbase = (smem_u32(dsm) + 1023u) & ~1023u;
    const int tid = threadIdx.x, wid = tid >> 5, lane = tid & 31;
    const int warp_m = wid & 3, warp_n = wid >> 2;
    const int m0 = blockIdx.y << 7, n0 = blockIdx.x << 7;
    const __nv_bfloat16* srcs[4] = {
        Ahi + (size_t)m0 * K, Alo + (size_t)m0 * K,
        Bhi + (size_t)n0 * K, Blo + (size_t)n0 * K };
    const int nch = K >> 6;

    auto load_chunk = [&](int c) {
        const uint32_t bb = sbase + ((c & 1) << 16);
        const int k0 = c << 6;
#pragma unroll
        for (int it = 0; it < 16; ++it) {
            int f = (it << 8) + tid;
            int p = f >> 10, q = f & 1023, r = q >> 3, g = q & 7;
            cpasync16(bb + (p << 14) + swz128((r << 7) + (g << 4)),
                      srcs[p] + (size_t)r * K + k0 + (g << 3));
        }
        CP_COMMIT();
    };

    float acc[2][8][4] = {};
    load_chunk(0);

    for (int c = 0; c < nch; ++c) {
        if (c + 1 < nch) { load_chunk(c + 1); CP_WAIT1(); }
        else             { CP_WAIT0(); }
        __syncthreads();
        const uint32_t bb = sbase + ((c & 1) << 16);
        const uint32_t pAh = bb, pAl = bb + 16384, pBh = bb + 32768, pBl = bb + 49152;
#pragma unroll
        for (int s = 0; s < 4; ++s) {
            uint32_t aH[2][4], aL[2][4];
#pragma unroll
            for (int mb = 0; mb < 2; ++mb) {
                int row = (warp_m << 5) + (mb << 4) + (lane & 15);
                int kseg = (s << 1) + (lane >> 4);
                uint32_t off = swz128((row << 7) + (kseg << 4));
                ldsm4(aH[mb], pAh + off);
                ldsm4(aL[mb], pAl + off);
            }
#pragma unroll
            for (int nbp = 0; nbp < 4; ++nbp) {
                int nrow = (warp_n << 6) + (nbp << 4) + (lane & 7) + ((lane >> 4) << 3);
                int kseg = (s << 1) + ((lane >> 3) & 1);
                uint32_t off = swz128((nrow << 7) + (kseg << 4));
                uint32_t bH[4], bL[4];
                ldsm4(bH, pBh + off);
                ldsm4(bL, pBl + off);
#pragma unroll
                for (int mb = 0; mb < 2; ++mb) {
#pragma unroll
                    for (int j = 0; j < 2; ++j) {
                        float* cc = acc[mb][(nbp << 1) + j];
                        mma16816(cc, aH[mb], bH + (j << 1));
                        mma16816(cc, aH[mb], bL + (j << 1));
                        mma16816(cc, aL[mb], bH + (j << 1));
                    }
                }
            }
        }
        __syncthreads();
    }

#pragma unroll
    for (int mb = 0; mb < 2; ++mb) {
        const int rbase = m0 + (warp_m << 5) + (mb << 4) + (lane >> 2);
#pragma unroll
        for (int nb = 0; nb < 8; ++nb) {
            const int col = n0 + (warp_n << 6) + (nb << 3) + ((lane & 3) << 1);
            const float b0 = bias[col], b1 = bias[col + 1];
#pragma unroll
            for (int half = 0; half < 2; ++half) {
                const int row = rbase + (half << 3);
                float vx = acc[mb][nb][(half << 1)] + b0;
                float vy = acc[mb][nb][(half << 1) + 1] + b1;
                if (mode == 0) {
                    *reinterpret_cast<float2*>(C + (size_t)row * N + col) = make_float2(vx, vy);
                } else {
                    const int bb_ = row >> 10, ss = row & 1023, h = col >> 6, d = col & 63;
                    __half2 hv = __floats2half2_rn(vx, vy);
                    *reinterpret_cast<__half2*>(
                        Ch + ((((size_t)((bb_ << 4) + h)) << 10) + ss) * 64 + d) = hv;
                }
            }
        }
    }
}

// QE = Qh @ rel^T. Qh:[QROWS,64] fp16, rel:[257,64] fp32 -> fp16 smem. Out fp32.
__global__ __launch_bounds__(128) void qe_mma(
    const __half* __restrict__ Qh, const float* __restrict__ rel, float* __restrict__ QE)
{
    extern __shared__ char dsm[];
    char* sp = dsm + ((1024 - (smem_u32(dsm) & 1023)) & 1023);
    const uint32_t sb = smem_u32(sp);
    const uint32_t uR = sb, uQ = sb + 34816;   // rel: 272 rows x 128B; Q: 8KB
    const int tid = threadIdx.x, w = tid >> 5, lane = tid & 31;
    const int m0 = blockIdx.x << 6;

    for (int i = tid; i < 2176; i += 128) {     // zero 34816B
        uint4 z = make_uint4(0, 0, 0, 0);
        STS128(uR + (i << 4), z);
    }
#pragma unroll
    for (int it = 0; it < 4; ++it) {
        int f = tid + (it << 7), row = f >> 3, g = f & 7;
        uint4 v = *reinterpret_cast<const uint4*>(Qh + (size_t)(m0 + row) * 64 + (g << 3));
        STS128(uQ + swz128((row << 7) + (g << 4)), v);
    }
    __syncthreads();
    for (int i = tid; i < RREL * 64; i += 128) {
        int row = i >> 6, col = i & 63;
        *reinterpret_cast<__half*>(sp + swz128((row << 7) + (col << 1))) = __float2half(rel[i]);
    }
    __syncthreads();

    uint32_t aq[4][4];
#pragma unroll
    for (int s = 0; s < 4; ++s)
        ldsm4(aq[s], uQ + swz128((((w << 4) + (lane & 15)) << 7) + (((s << 1) + (lane >> 4)) << 4)));

    const int r0 = m0 + (w << 4) + (lane >> 2);
    for (int nbp = 0; nbp < 17; ++nbp) {
        float a0[4] = {}, a1[4] = {};
#pragma unroll
        for (int s = 0; s < 4; ++s) {
            uint32_t bb[4];
            ldsm4(bb, uR + swz128((((nbp << 4) + (lane & 7) + ((lane >> 4) << 3)) << 7)
                                  + (((s << 1) + ((lane >> 3) & 1)) << 4)));
            mma16816h(a0, aq[s], bb);
            mma16816h(a1, aq[s], bb + 2);
        }
#pragma unroll
        for (int j = 0; j < 2; ++j) {
            float* a = j ? a1 : a0;
            int col = ((nbp << 1) + j) * 8 + ((lane & 3) << 1);
            if (col < RREL) {
                size_t b0 = (size_t)r0 * RREL + col;
                QE[b0] = a[0];
                QE[b0 + 8 * RREL] = a[2];
                if (col + 1 < RREL) { QE[b0 + 1] = a[1]; QE[b0 + 8 * RREL + 1] = a[3]; }
            }
        }
    }
}

// Flash attention, fp16 mma, rel-pos bias from smem QE. grid(64 bh, 16 qtiles), 128 thr.
__global__ __launch_bounds__(128) void flash_mma(
    const __half* __restrict__ Qh, const __half* __restrict__ Kh,
    const __half* __restrict__ Vh, const float* __restrict__ QE)
{
    extern __shared__ char dsm[];
    char* sp = dsm + ((1024 - (smem_u32(dsm) & 1023)) & 1023);
    const uint32_t sb = smem_u32(sp);
    float* QEs = reinterpret_cast<float*>(sp);          // 64 x 260 fp32 = 66560B
    const uint32_t uQ = sb + 66560;                     // 8KB
    const uint32_t uK0 = sb + 74752, uV0 = sb + 91136;  // 2x8KB each
    const int tid = threadIdx.x, w = tid >> 5, lane = tid & 31;
    const int bh = blockIdx.x, q0 = blockIdx.y << 6;
    const __half* Qb = Qh + ((size_t)bh * 1024 + q0) * 64;
    const __half* Kb = Kh + (size_t)bh * 1024 * 64;
    const __half* Vb = Vh + (size_t)bh * 1024 * 64;
    const float* QEg = QE + ((size_t)bh * 1024 + q0) * RREL;

    auto prefetch = [&](int kt) {
        const int buf = kt & 1;
        const uint32_t dK = uK0 + (buf << 13), dV = uV0 + (buf << 13);
        const int k0 = kt << 6;
#pragma unroll
        for (int it = 0; it < 4; ++it) {
            int f = tid + (it << 7), row = f >> 3, g = f & 7;
            uint32_t off = swz128((row << 7) + (g << 4));
            cpasync16(dK + off, Kb + (size_t)(k0 + row) * 64 + (g << 3));
            cpasync16(dV + off, Vb + (size_t)(k0 + row) * 64 + (g << 3));
        }
        CP_COMMIT();
    };

    prefetch(0);
#pragma unroll
    for (int it = 0; it < 4; ++it) {
        int f = tid + (it << 7), row = f >> 3, g = f & 7;
        uint4 v = *reinterpret_cast<const uint4*>(Qb + (size_t)row * 64 + (g << 3));
        STS128(uQ + swz128((row << 7) + (g << 4)), v);
    }
    for (int r = 0; r < 64; ++r)
        for (int j = tid; j < RREL; j += 128)
            QEs[r * 260 + j] = QEg[(size_t)r * RREL + j];
    __syncthreads();

    uint32_t aq[4][4];
#pragma unroll
    for (int s = 0; s < 4; ++s)
        ldsm4(aq[s], uQ + swz128((((w << 4) + (lane & 15)) << 7) + (((s << 1) + (lane >> 4)) << 4)));

    float acc_o[8][4] = {};
    float m0v = -1e30f, m1v = -1e30f, l0v = 0.f, l1v = 0.f;
    const int qg0 = q0 + (w << 4) + (lane >> 2);
    const float* QEr0 = QEs + ((w << 4) + (lane >> 2)) * 260 + 128;
    const float* QEr1 = QEr0 + 8 * 260;

    for (int kt = 0; kt < 16; ++kt) {
        if (kt + 1 < 16) { prefetch(kt + 1); CP_WAIT1(); }
        else             { CP_WAIT0(); }
        __syncthreads();
        const int buf = kt & 1;
        const uint32_t bK = uK0 + (buf << 13), bV = uV0 + (buf << 13);

        float s_[8][4] = {};
#pragma unroll
        for (int s = 0; s < 4; ++s) {
#pragma unroll
            for (int nbp = 0; nbp < 4; ++nbp) {
                uint32_t bb[4];
                ldsm4(bb, bK + swz128((((nbp << 4) + (lane & 7) + ((lane >> 4) << 3)) << 7)
                                      + (((s << 1) + ((lane >> 3) & 1)) << 4)));
                mma16816h(s_[2 * nbp], aq[s], bb);
                mma16816h(s_[2 * nbp + 1], aq[s], bb + 2);
            }
        }
        const int k0 = kt << 6;
        float mt0 = -1e30f, mt1 = -1e30f;
#pragma unroll
        for (int nb = 0; nb < 8; ++nb) {
            int d00 = k0 + (nb << 3) + ((lane & 3) << 1) - qg0;
            int r00 = min(max(d00,     -128), 128), r01 = min(max(d00 + 1, -128), 128);
            int r10 = min(max(d00 - 8, -128), 128), r11 = min(max(d00 - 7, -128), 128);
            s_[nb][0] = (s_[nb][0] + QEr0[r00]) * 0.125f;
            s_[nb][1] = (s_[nb][1] + QEr0[r01]) * 0.125f;
            s_[nb][2] = (s_[nb][2] + QEr1[r10]) * 0.125f;
            s_[nb][3] = (s_[nb][3] + QEr1[r11]) * 0.125f;
            mt0 = fmaxf(mt0, fmaxf(s_[nb][0], s_[nb][1]));
            mt1 = fmaxf(mt1, fmaxf(s_[nb][2], s_[nb][3]));
        }
        mt0 = fmaxf(mt0, __shfl_xor_sync(~0u, mt0, 1));
        mt0 = fmaxf(mt0, __shfl_xor_sync(~0u, mt0, 2));
        mt1 = fmaxf(mt1, __shfl_xor_sync(~0u, mt1, 1));
        mt1 = fmaxf(mt1, __shfl_xor_sync(~0u, mt1, 2));
        float mn0 = fmaxf(m0v, mt0), mn1 = fmaxf(m1v, mt1);
        float al0 = __expf(m0v - mn0), al1 = __expf(m1v - mn1);
        float rs0 = 0.f, rs1 = 0.f;
        uint32_t ph[4][4];
#pragma unroll
        for (int nb = 0; nb < 8; ++nb) {
            float p0 = __expf(s_[nb][0] - mn0), p1 = __expf(s_[nb][1] - mn0);
            float p2 = __expf(s_[nb][2] - mn1), p3 = __expf(s_[nb][3] - mn1);
            rs0 += p0 + p1; rs1 += p2 + p3;
            __half2 h01 = __floats2half2_rn(p0, p1), h23 = __floats2half2_rn(p2, p3);
            int s = nb >> 1, base = (nb & 1) << 1;
            ph[s][base]     = *reinterpret_cast<uint32_t*>(&h01);
            ph[s][base + 1] = *reinterpret_cast<uint32_t*>(&h23);
        }
        rs0 += __shfl_xor_sync(~0u, rs0, 1); rs0 += __shfl_xor_sync(~0u, rs0, 2);
        rs1 += __shfl_xor_sync(~0u, rs1, 1); rs1 += __shfl_xor_sync(~0u, rs1, 2);
        l0v = l0v * al0 + rs0; l1v = l1v * al1 + rs1;
        m0v = mn0; m1v = mn1;
#pragma unroll
        for (int nd = 0; nd < 8; ++nd) {
            acc_o[nd][0] *= al0; acc_o[nd][1] *= al0;
            acc_o[nd][2] *= al1; acc_o[nd][3] *= al1;
        }
#pragma unroll
        for (int s = 0; s < 4; ++s) {
#pragma unroll
            for (int ndp = 0; ndp < 4; ++ndp) {
                uint32_t bv[4];
                ldsm4t(bv, bV + swz128((((s << 4) + (lane & 15)) << 7)
                                       + (((ndp << 4) + ((lane >> 4) << 3)) << 1)));
                mma16816h(acc_o[2 * ndp],     ph[s], bv);
                mma16816h(acc_o[2 * ndp + 1], ph[s], bv + 2);
            }
        }
        __syncthreads();
    }

    const int b = bh >> 4, h = bh & 15;
    const float inv0 = 1.f / l0v, inv1 = 1.f / l1v;
#pragma unroll
    for (int nd = 0; nd < 8; ++nd) {
        int d = (nd << 3) + ((lane & 3) << 1);
        float* p0 = g_AO + (((size_t)(b << 10) + qg0) << 10) + (h << 6) + d;
        *reinterpret_cast<float2*>(p0) = make_float2(acc_o[nd][0] * inv0, acc_o[nd][1] * inv0);
        *reinterpret_cast<float2*>(p0 + (8 << 10)) =
            make_float2(acc_o[nd][2] * inv1, acc_o[nd][3] * inv1);
    }
}

extern "C" void kernel_launch(void* const* d_in, const int* in_sizes, int n_in,
                              void* d_out, int out_size) {
    const float* x   = (const float*)d_in[0];
    const float* Wq  = (const float*)d_in[1];
    const float* bq  = (const float*)d_in[2];
    const float* Wk  = (const float*)d_in[3];
    const float* bk  = (const float*)d_in[4];
    const float* Wv  = (const float*)d_in[5];
    const float* bv  = (const float*)d_in[6];
    const float* Wo  = (const float*)d_in[7];
    const float* bo  = (const float*)d_in[8];
    const float* rel = (const float*)d_in[9];
    float* out = (float*)d_out;

    float *QEp, *AOp;
    __half *Qh, *Kh, *Vh;
    __nv_bfloat16 *xhi, *xlo, *whi, *wlo, *aohi, *aolo;
    cudaGetSymbolAddress((void**)&QEp, g_QE);
    cudaGetSymbolAddress((void**)&AOp, g_AO);
    cudaGetSymbolAddress((void**)&Qh, g_Qh);
    cudaGetSymbolAddress((void**)&Kh, g_Kh);
    cudaGetSymbolAddress((void**)&Vh, g_Vh);
    cudaGetSymbolAddress((void**)&xhi, g_xhi);
    cudaGetSymbolAddress((void**)&xlo, g_xlo);
    cudaGetSymbolAddress((void**)&whi, g_whi);
    cudaGetSymbolAddress((void**)&wlo, g_wlo);
    cudaGetSymbolAddress((void**)&aohi, g_aohi);
    cudaGetSymbolAddress((void**)&aolo, g_aolo);

    static int once = 0;
    const int smem_mm = 132096;
    const int smem_fl = 108544;
    const int smem_qe = 44032;
    if (!once) {
        cudaFuncSetAttribute(gemm_mma, cudaFuncAttributeMaxDynamicSharedMemorySize, smem_mm);
        cudaFuncSetAttribute(flash_mma, cudaFuncAttributeMaxDynamicSharedMemorySize, smem_fl);
        cudaFuncSetAttribute(qe_mma, cudaFuncAttributeMaxDynamicSharedMemorySize, smem_qe);
        once = 1;
    }

    const int NW = 1024 * 1024;
    splitk<<<(MROWS * 1024 + 255) / 256, 256>>>(x,  xhi, xlo, MROWS * 1024);
    splitk<<<(NW + 255) / 256, 256>>>(Wq, whi,          wlo,          NW);
    splitk<<<(NW + 255) / 256, 256>>>(Wk, whi + NW,     wlo + NW,     NW);
    splitk<<<(NW + 255) / 256, 256>>>(Wv, whi + 2 * NW, wlo + 2 * NW, NW);
    splitk<<<(NW + 255) / 256, 256>>>(Wo, whi + 3 * NW, wlo + 3 * NW, NW);

    dim3 gmm(8, 32);
    gemm_mma<<<gmm, 256, smem_mm>>>(xhi, xlo, whi,          wlo,          bq, nullptr, Qh, 1024, 1024, 1);
    gemm_mma<<<gmm, 256, smem_mm>>>(xhi, xlo, whi + NW,     wlo + NW,     bk, nullptr, Kh, 1024, 1024, 1);
    gemm_mma<<<gmm, 256, smem_mm>>>(xhi, xlo, whi + 2 * NW, wlo + 2 * NW, bv, nullptr, Vh, 1024, 1024, 1);

    qe_mma<<<1024, 128, smem_qe>>>(Qh, rel, QEp);
    flash_mma<<<dim3(64, 16), 128, smem_fl>>>(Qh, Kh, Vh, QEp);

    splitk<<<(MROWS * 1024 + 255) / 256, 256>>>(AOp, aohi, aolo, MROWS * 1024);
    gemm_mma<<<gmm, 256, smem_mm>>>(aohi, aolo, whi + 3 * NW, wlo + 3 * NW, bo, out, nullptr, 1024, 1024, 0);

    (void)in_sizes; (void)n_in; (void)out_size;
}

// round 6
// speedup vs baseline: 4.1159x; 1.5127x over previous
#include <cuda_runtime.h>
#include <cuda_bf16.h>
#include <cuda_fp16.h>
#include <cstdint>

#define NH 16
#define MROWS 4096
#define QROWS 65536
#define RREL 257
#define QESTR 260

__device__ __half g_QEh[(size_t)QROWS * QESTR];
__device__ __half g_Qh[QROWS * 64], g_Kh[QROWS * 64], g_Vh[QROWS * 64];
__device__ __nv_bfloat16 g_xhi[MROWS * 1024], g_xlo[MROWS * 1024];
__device__ __nv_bfloat16 g_whi[4 * 1024 * 1024], g_wlo[4 * 1024 * 1024];
__device__ __nv_bfloat16 g_aohi[MROWS * 1024], g_aolo[MROWS * 1024];

__device__ __forceinline__ uint32_t smem_u32(const void* p) {
    uint32_t a;
    asm("{ .reg .u64 t; cvta.to.shared.u64 t, %1; cvt.u32.u64 %0, t; }" : "=r"(a) : "l"(p));
    return a;
}
__device__ __forceinline__ uint32_t swz128(uint32_t b) { return b ^ ((b >> 3) & 0x70); }
__device__ __forceinline__ void ldsm4(uint32_t* r, uint32_t a) {
    asm volatile("ldmatrix.sync.aligned.m8n8.x4.shared.b16 {%0,%1,%2,%3}, [%4];"
                 : "=r"(r[0]), "=r"(r[1]), "=r"(r[2]), "=r"(r[3]) : "r"(a));
}
__device__ __forceinline__ void ldsm4t(uint32_t* r, uint32_t a) {
    asm volatile("ldmatrix.sync.aligned.m8n8.x4.trans.shared.b16 {%0,%1,%2,%3}, [%4];"
                 : "=r"(r[0]), "=r"(r[1]), "=r"(r[2]), "=r"(r[3]) : "r"(a));
}
__device__ __forceinline__ void mma16816(float* c, const uint32_t* a, const uint32_t* b) {
    asm volatile(
        "mma.sync.aligned.m16n8k16.row.col.f32.bf16.bf16.f32 "
        "{%0,%1,%2,%3},{%4,%5,%6,%7},{%8,%9},{%0,%1,%2,%3};"
        : "+f"(c[0]), "+f"(c[1]), "+f"(c[2]), "+f"(c[3])
        : "r"(a[0]), "r"(a[1]), "r"(a[2]), "r"(a[3]), "r"(b[0]), "r"(b[1]));
}
__device__ __forceinline__ void mma16816h(float* c, const uint32_t* a, const uint32_t* b) {
    asm volatile(
        "mma.sync.aligned.m16n8k16.row.col.f32.f16.f16.f32 "
        "{%0,%1,%2,%3},{%4,%5,%6,%7},{%8,%9},{%0,%1,%2,%3};"
        : "+f"(c[0]), "+f"(c[1]), "+f"(c[2]), "+f"(c[3])
        : "r"(a[0]), "r"(a[1]), "r"(a[2]), "r"(a[3]), "r"(b[0]), "r"(b[1]));
}
__device__ __forceinline__ void cpasync16(uint32_t sa, const void* ga) {
    asm volatile("cp.async.cg.shared.global [%0], [%1], 16;" :: "r"(sa), "l"(ga));
}
#define CP_COMMIT() asm volatile("cp.async.commit_group;" ::: "memory")
#define CP_WAIT1()  asm volatile("cp.async.wait_group 1;" ::: "memory")
#define CP_WAIT0()  asm volatile("cp.async.wait_group 0;" ::: "memory")
#define STS128(a, v) asm volatile("st.shared.v4.b32 [%0], {%1,%2,%3,%4};" \
    :: "r"(a), "r"(v.x), "r"(v.y), "r"(v.z), "r"(v.w) : "memory")

// One fused split: x (4M) then Wq|Wk|Wv|Wo (4 x 1M) -> bf16 hi/lo.
__global__ void splitall(const float* __restrict__ x,
                         const float* __restrict__ Wq, const float* __restrict__ Wk,
                         const float* __restrict__ Wv, const float* __restrict__ Wo,
                         __nv_bfloat16* __restrict__ xhi, __nv_bfloat16* __restrict__ xlo,
                         __nv_bfloat16* __restrict__ whi, __nv_bfloat16* __restrict__ wlo) {
    int i = blockIdx.x * blockDim.x + threadIdx.x;
    const int NX = MROWS * 1024;
    float v;
    __nv_bfloat16* ph;
    __nv_bfloat16* pl;
    int o;
    if (i < NX) { v = x[i]; ph = xhi; pl = xlo; o = i; }
    else {
        int j = i - NX;
        int w = j >> 20, k = j & 1048575;
        const float* s = (w == 0) ? Wq : (w == 1) ? Wk : (w == 2) ? Wv : Wo;
        v = s[k]; ph = whi; pl = wlo; o = j;
    }
    __nv_bfloat16 h = __float2bfloat16(v);
    ph[o] = h;
    pl[o] = __float2bfloat16(v - __bfloat162float(h));
}

// C = (Ahi+Alo)@(Bhi+Blo)^T + bias, 3-term bf16 split. Tile 128x128, Kchunk 64.
// mode0: fp32 C[m*N+n] (bias b0). mode1: fp16 into Qh/Kh/Vh by proj=col>>10, bias b0/b1/b2.
__global__ __launch_bounds__(256) void gemm_mma(
    const __nv_bfloat16* __restrict__ Ahi, const __nv_bfloat16* __restrict__ Alo,
    const __nv_bfloat16* __restrict__ Bhi, const __nv_bfloat16* __restrict__ Blo,
    const float* __restrict__ b0p, const float* __restrict__ b1p, const float* __restrict__ b2p,
    float* __restrict__ C, __half* __restrict__ Qh, __half* __restrict__ Kh, __half* __restrict__ Vh,
    int K, int N, int noff, int mode)
{
    extern __shared__ char dsm[];
    const uint32_t sbase = (smem_u32(dsm) + 1023u) & ~1023u;
    const int tid = threadIdx.x, wid = tid >> 5, lane = tid & 31;
    const int warp_m = wid & 3, warp_n = wid >> 2;
    const int m0 = blockIdx.y << 7, n0 = (blockIdx.x << 7) + noff;
    const __nv_bfloat16* srcs[4] = {
        Ahi + (size_t)m0 * K, Alo + (size_t)m0 * K,
        Bhi + (size_t)n0 * K, Blo + (size_t)n0 * K };
    const int nch = K >> 6;

    auto load_chunk = [&](int c) {
        const uint32_t bb = sbase + ((c & 1) << 16);
        const int k0 = c << 6;
#pragma unroll
        for (int it = 0; it < 16; ++it) {
            int f = (it << 8) + tid;
            int p = f >> 10, q = f & 1023, r = q >> 3, g = q & 7;
            cpasync16(bb + (p << 14) + swz128((r << 7) + (g << 4)),
                      srcs[p] + (size_t)r * K + k0 + (g << 3));
        }
        CP_COMMIT();
    };

    float acc[2][8][4] = {};
    load_chunk(0);

    for (int c = 0; c < nch; ++c) {
        if (c + 1 < nch) { load_chunk(c + 1); CP_WAIT1(); }
        else             { CP_WAIT0(); }
        __syncthreads();
        const uint32_t bb = sbase + ((c & 1) << 16);
        const uint32_t pAh = bb, pAl = bb + 16384, pBh = bb + 32768, pBl = bb + 49152;
#pragma unroll
        for (int s = 0; s < 4; ++s) {
            uint32_t aH[2][4], aL[2][4];
#pragma unroll
            for (int mb = 0; mb < 2; ++mb) {
                int row = (warp_m << 5) + (mb << 4) + (lane & 15);
                int kseg = (s << 1) + (lane >> 4);
                uint32_t off = swz128((row << 7) + (kseg << 4));
                ldsm4(aH[mb], pAh + off);
                ldsm4(aL[mb], pAl + off);
            }
#pragma unroll
            for (int nbp = 0; nbp < 4; ++nbp) {
                int nrow = (warp_n << 6) + (nbp << 4) + (lane & 7) + ((lane >> 4) << 3);
                int kseg = (s << 1) + ((lane >> 3) & 1);
                uint32_t off = swz128((nrow << 7) + (kseg << 4));
                uint32_t bH[4], bL[4];
                ldsm4(bH, pBh + off);
                ldsm4(bL, pBl + off);
#pragma unroll
                for (int mb = 0; mb < 2; ++mb) {
#pragma unroll
                    for (int j = 0; j < 2; ++j) {
                        float* cc = acc[mb][(nbp << 1) + j];
                        mma16816(cc, aH[mb], bH + (j << 1));
                        mma16816(cc, aH[mb], bL + (j << 1));
                        mma16816(cc, aL[mb], bH + (j << 1));
                    }
                }
            }
        }
        __syncthreads();
    }

#pragma unroll
    for (int mb = 0; mb < 2; ++mb) {
        const int rbase = m0 + (warp_m << 5) + (mb << 4) + (lane >> 2);
#pragma unroll
        for (int nb = 0; nb < 8; ++nb) {
            const int col = n0 + (warp_n << 6) + (nb << 3) + ((lane & 3) << 1);
            if (mode == 0) {
                const float bb0 = b0p[col], bb1 = b0p[col + 1];
#pragma unroll
                for (int half = 0; half < 2; ++half) {
                    const int row = rbase + (half << 3);
                    *reinterpret_cast<float2*>(C + (size_t)row * N + col) =
                        make_float2(acc[mb][nb][(half << 1)] + bb0,
                                    acc[mb][nb][(half << 1) + 1] + bb1);
                }
            } else {
                const int proj = col >> 10, cc = col & 1023, h = cc >> 6, d = cc & 63;
                __half* dst = (proj == 0) ? Qh : (proj == 1) ? Kh : Vh;
                const float* bs = (proj == 0) ? b0p : (proj == 1) ? b1p : b2p;
                const float bb0 = bs[cc], bb1 = bs[cc + 1];
#pragma unroll
                for (int half = 0; half < 2; ++half) {
                    const int row = rbase + (half << 3);
                    const int bb_ = row >> 10, ss = row & 1023;
                    *reinterpret_cast<__half2*>(
                        dst + ((((size_t)((bb_ << 4) + h)) << 10) + ss) * 64 + d) =
                        __floats2half2_rn(acc[mb][nb][(half << 1)] + bb0,
                                          acc[mb][nb][(half << 1) + 1] + bb1);
                }
            }
        }
    }
}

// QE = Qh @ rel^T, fp16 out with row stride 260.
__global__ __launch_bounds__(128) void qe_mma(
    const __half* __restrict__ Qh, const float* __restrict__ rel, __half* __restrict__ QE)
{
    extern __shared__ char dsm[];
    char* sp = dsm + ((1024 - (smem_u32(dsm) & 1023)) & 1023);
    const uint32_t sb = smem_u32(sp);
    const uint32_t uR = sb, uQ = sb + 34816;
    const int tid = threadIdx.x, w = tid >> 5, lane = tid & 31;
    const int m0 = blockIdx.x << 6;

    for (int i = tid; i < 2176; i += 128) {
        uint4 z = make_uint4(0, 0, 0, 0);
        STS128(uR + (i << 4), z);
    }
#pragma unroll
    for (int it = 0; it < 4; ++it) {
        int f = tid + (it << 7), row = f >> 3, g = f & 7;
        uint4 v = *reinterpret_cast<const uint4*>(Qh + (size_t)(m0 + row) * 64 + (g << 3));
        STS128(uQ + swz128((row << 7) + (g << 4)), v);
    }
    __syncthreads();
    for (int i = tid; i < RREL * 64; i += 128) {
        int row = i >> 6, col = i & 63;
        *reinterpret_cast<__half*>(sp + swz128((row << 7) + (col << 1))) = __float2half(rel[i]);
    }
    __syncthreads();

    uint32_t aq[4][4];
#pragma unroll
    for (int s = 0; s < 4; ++s)
        ldsm4(aq[s], uQ + swz128((((w << 4) + (lane & 15)) << 7) + (((s << 1) + (lane >> 4)) << 4)));

    const int r0 = m0 + (w << 4) + (lane >> 2);
    for (int nbp = 0; nbp < 17; ++nbp) {
        float a0[4] = {}, a1[4] = {};
#pragma unroll
        for (int s = 0; s < 4; ++s) {
            uint32_t bb[4];
            ldsm4(bb, uR + swz128((((nbp << 4) + (lane & 7) + ((lane >> 4) << 3)) << 7)
                                  + (((s << 1) + ((lane >> 3) & 1)) << 4)));
            mma16816h(a0, aq[s], bb);
            mma16816h(a1, aq[s], bb + 2);
        }
#pragma unroll
        for (int j = 0; j < 2; ++j) {
            float* a = j ? a1 : a0;
            int col = ((nbp << 1) + j) * 8 + ((lane & 3) << 1);
            if (col <= 256) {
                *reinterpret_cast<__half2*>(QE + (size_t)r0 * QESTR + col) =
                    __floats2half2_rn(a[0], a[1]);
                *reinterpret_cast<__half2*>(QE + (size_t)(r0 + 8) * QESTR + col) =
                    __floats2half2_rn(a[2], a[3]);
            }
        }
    }
}

// Flash attention, fp16 mma, fp16 QE bias from smem. grid(64 bh, 16 qtiles), 128 thr.
// Epilogue writes bf16 hi/lo split of AO directly.
__global__ __launch_bounds__(128) void flash_mma(
    const __half* __restrict__ Qh, const __half* __restrict__ Kh,
    const __half* __restrict__ Vh, const __half* __restrict__ QE,
    __nv_bfloat16* __restrict__ AOhi, __nv_bfloat16* __restrict__ AOlo)
{
    extern __shared__ char dsm[];
    char* sp = dsm + ((1024 - (smem_u32(dsm) & 1023)) & 1023);
    const uint32_t sb = smem_u32(sp);
    __half* QEs = reinterpret_cast<__half*>(sp);        // 64 x 260 fp16 = 33280B
    const uint32_t uQ = sb + 33280;                     // 8KB
    const uint32_t uK0 = sb + 41472, uV0 = sb + 57856;  // 2x8KB each
    const int tid = threadIdx.x, w = tid >> 5, lane = tid & 31;
    const int bh = blockIdx.x, q0 = blockIdx.y << 6;
    const __half* Qb = Qh + ((size_t)bh * 1024 + q0) * 64;
    const __half* Kb = Kh + (size_t)bh * 1024 * 64;
    const __half* Vb = Vh + (size_t)bh * 1024 * 64;

    auto prefetch = [&](int kt) {
        const int buf = kt & 1;
        const uint32_t dK = uK0 + (buf << 13), dV = uV0 + (buf << 13);
        const int k0 = kt << 6;
#pragma unroll
        for (int it = 0; it < 4; ++it) {
            int f = tid + (it << 7), row = f >> 3, g = f & 7;
            uint32_t off = swz128((row << 7) + (g << 4));
            cpasync16(dK + off, Kb + (size_t)(k0 + row) * 64 + (g << 3));
            cpasync16(dV + off, Vb + (size_t)(k0 + row) * 64 + (g << 3));
        }
        CP_COMMIT();
    };

    prefetch(0);
#pragma unroll
    for (int it = 0; it < 4; ++it) {
        int f = tid + (it << 7), row = f >> 3, g = f & 7;
        uint4 v = *reinterpret_cast<const uint4*>(Qb + (size_t)row * 64 + (g << 3));
        STS128(uQ + swz128((row << 7) + (g << 4)), v);
    }
    {   // flat copy of 64x260 fp16 QE slice (rows contiguous), 8B chunks
        const uint2* src = reinterpret_cast<const uint2*>(QE + ((size_t)bh * 1024 + q0) * QESTR);
        uint2* dst = reinterpret_cast<uint2*>(QEs);
        for (int i = tid; i < 4160; i += 128) dst[i] = src[i];
    }
    __syncthreads();

    uint32_t aq[4][4];
#pragma unroll
    for (int s = 0; s < 4; ++s)
        ldsm4(aq[s], uQ + swz128((((w << 4) + (lane & 15)) << 7) + (((s << 1) + (lane >> 4)) << 4)));

    float acc_o[8][4] = {};
    float m0v = -1e30f, m1v = -1e30f, l0v = 0.f, l1v = 0.f;
    const int qg0 = q0 + (w << 4) + (lane >> 2);
    const __half* QEr0 = QEs + ((w << 4) + (lane >> 2)) * QESTR + 128;
    const __half* QEr1 = QEr0 + 8 * QESTR;

    for (int kt = 0; kt < 16; ++kt) {
        if (kt + 1 < 16) { prefetch(kt + 1); CP_WAIT1(); }
        else             { CP_WAIT0(); }
        __syncthreads();
        const int buf = kt & 1;
        const uint32_t bK = uK0 + (buf << 13), bV = uV0 + (buf << 13);

        float s_[8][4] = {};
#pragma unroll
        for (int s = 0; s < 4; ++s) {
#pragma unroll
            for (int nbp = 0; nbp < 4; ++nbp) {
                uint32_t bb[4];
                ldsm4(bb, bK + swz128((((nbp << 4) + (lane & 7) + ((lane >> 4) << 3)) << 7)
                                      + (((s << 1) + ((lane >> 3) & 1)) << 4)));
                mma16816h(s_[2 * nbp], aq[s], bb);
                mma16816h(s_[2 * nbp + 1], aq[s], bb + 2);
            }
        }
        const int k0 = kt << 6;
        float mt0 = -1e30f, mt1 = -1e30f;
#pragma unroll
        for (int nb = 0; nb < 8; ++nb) {
            int d00 = k0 + (nb << 3) + ((lane & 3) << 1) - qg0;
            int r00 = min(max(d00,     -128), 128), r01 = min(max(d00 + 1, -128), 128);
            int r10 = min(max(d00 - 8, -128), 128), r11 = min(max(d00 - 7, -128), 128);
            s_[nb][0] = (s_[nb][0] + __half2float(QEr0[r00])) * 0.125f;
            s_[nb][1] = (s_[nb][1] + __half2float(QEr0[r01])) * 0.125f;
            s_[nb][2] = (s_[nb][2] + __half2float(QEr1[r10])) * 0.125f;
            s_[nb][3] = (s_[nb][3] + __half2float(QEr1[r11])) * 0.125f;
            mt0 = fmaxf(mt0, fmaxf(s_[nb][0], s_[nb][1]));
            mt1 = fmaxf(mt1, fmaxf(s_[nb][2], s_[nb][3]));
        }
        mt0 = fmaxf(mt0, __shfl_xor_sync(~0u, mt0, 1));
        mt0 = fmaxf(mt0, __shfl_xor_sync(~0u, mt0, 2));
        mt1 = fmaxf(mt1, __shfl_xor_sync(~0u, mt1, 1));
        mt1 = fmaxf(mt1, __shfl_xor_sync(~0u, mt1, 2));
        float mn0 = fmaxf(m0v, mt0), mn1 = fmaxf(m1v, mt1);
        float al0 = __expf(m0v - mn0), al1 = __expf(m1v - mn1);
        float rs0 = 0.f, rs1 = 0.f;
        uint32_t ph[4][4];
#pragma unroll
        for (int nb = 0; nb < 8; ++nb) {
            float p0 = __expf(s_[nb][0] - mn0), p1 = __expf(s_[nb][1] - mn0);
            float p2 = __expf(s_[nb][2] - mn1), p3 = __expf(s_[nb][3] - mn1);
            rs0 += p0 + p1; rs1 += p2 + p3;
            __half2 h01 = __floats2half2_rn(p0, p1), h23 = __floats2half2_rn(p2, p3);
            int s = nb >> 1, base = (nb & 1) << 1;
            ph[s][base]     = *reinterpret_cast<uint32_t*>(&h01);
            ph[s][base + 1] = *reinterpret_cast<uint32_t*>(&h23);
        }
        rs0 += __shfl_xor_sync(~0u, rs0, 1); rs0 += __shfl_xor_sync(~0u, rs0, 2);
        rs1 += __shfl_xor_sync(~0u, rs1, 1); rs1 += __shfl_xor_sync(~0u, rs1, 2);
        l0v = l0v * al0 + rs0; l1v = l1v * al1 + rs1;
        m0v = mn0; m1v = mn1;
#pragma unroll
        for (int nd = 0; nd < 8; ++nd) {
            acc_o[nd][0] *= al0; acc_o[nd][1] *= al0;
            acc_o[nd][2] *= al1; acc_o[nd][3] *= al1;
        }
#pragma unroll
        for (int s = 0; s < 4; ++s) {
#pragma unroll
            for (int ndp = 0; ndp < 4; ++ndp) {
                uint32_t bv[4];
                ldsm4t(bv, bV + swz128((((s << 4) + (lane & 15)) << 7)
                                       + (((ndp << 4) + ((lane >> 4) << 3)) << 1)));
                mma16816h(acc_o[2 * ndp],     ph[s], bv);
                mma16816h(acc_o[2 * ndp + 1], ph[s], bv + 2);
            }
        }
        __syncthreads();
    }

    const int b = bh >> 4, h = bh & 15;
    const float inv0 = 1.f / l0v, inv1 = 1.f / l1v;
#pragma unroll
    for (int nd = 0; nd < 8; ++nd) {
        int d = (nd << 3) + ((lane & 3) << 1);
        size_t o0 = (((size_t)(b << 10) + qg0) << 10) + (h << 6) + d;
#pragma unroll
        for (int half = 0; half < 2; ++half) {
            float vx = acc_o[nd][(half << 1)] * (half ? inv1 : inv0);
            float vy = acc_o[nd][(half << 1) + 1] * (half ? inv1 : inv0);
            size_t o = o0 + ((size_t)(half << 3) << 10);
            __nv_bfloat16 hx = __float2bfloat16(vx), hy = __float2bfloat16(vy);
            *reinterpret_cast<__nv_bfloat162*>(AOhi + o) = __nv_bfloat162(hx, hy);
            *reinterpret_cast<__nv_bfloat162*>(AOlo + o) = __nv_bfloat162(
                __float2bfloat16(vx - __bfloat162float(hx)),
                __float2bfloat16(vy - __bfloat162float(hy)));
        }
    }
}

extern "C" void kernel_launch(void* const* d_in, const int* in_sizes, int n_in,
                              void* d_out, int out_size) {
    const float* x   = (const float*)d_in[0];
    const float* Wq  = (const float*)d_in[1];
    const float* bq  = (const float*)d_in[2];
    const float* Wk  = (const float*)d_in[3];
    const float* bk  = (const float*)d_in[4];
    const float* Wv  = (const float*)d_in[5];
    const float* bv  = (const float*)d_in[6];
    const float* Wo  = (const float*)d_in[7];
    const float* bo  = (const float*)d_in[8];
    const float* rel = (const float*)d_in[9];
    float* out = (float*)d_out;

    __half *QEp, *Qh, *Kh, *Vh;
    __nv_bfloat16 *xhi, *xlo, *whi, *wlo, *aohi, *aolo;
    cudaGetSymbolAddress((void**)&QEp, g_QEh);
    cudaGetSymbolAddress((void**)&Qh, g_Qh);
    cudaGetSymbolAddress((void**)&Kh, g_Kh);
    cudaGetSymbolAddress((void**)&Vh, g_Vh);
    cudaGetSymbolAddress((void**)&xhi, g_xhi);
    cudaGetSymbolAddress((void**)&xlo, g_xlo);
    cudaGetSymbolAddress((void**)&whi, g_whi);
    cudaGetSymbolAddress((void**)&wlo, g_wlo);
    cudaGetSymbolAddress((void**)&aohi, g_aohi);
    cudaGetSymbolAddress((void**)&aolo, g_aolo);

    static cudaStream_t s1 = nullptr;
    static cudaEvent_t e0 = nullptr, e1 = nullptr;
    static int once = 0;
    const int smem_mm = 132096;
    const int smem_fl = 75264;
    const int smem_qe = 44032;
    if (!once) {
        cudaFuncSetAttribute(gemm_mma, cudaFuncAttributeMaxDynamicSharedMemorySize, smem_mm);
        cudaFuncSetAttribute(flash_mma, cudaFuncAttributeMaxDynamicSharedMemorySize, smem_fl);
        cudaFuncSetAttribute(qe_mma, cudaFuncAttributeMaxDynamicSharedMemorySize, smem_qe);
        cudaStreamCreateWithFlags(&s1, cudaStreamNonBlocking);
        cudaEventCreateWithFlags(&e0, cudaEventDisableTiming);
        cudaEventCreateWithFlags(&e1, cudaEventDisableTiming);
        once = 1;
    }

    splitall<<<32768, 256>>>(x, Wq, Wk, Wv, Wo, xhi, xlo, whi, wlo);

    // Q projection (cols 0..1023)
    gemm_mma<<<dim3(8, 32), 256, smem_mm>>>(xhi, xlo, whi, wlo, bq, bk, bv,
                                            nullptr, Qh, Kh, Vh, 1024, 1024, 0, 1);
    // fork: qe (needs Q only) || K,V projections (cols 1024..3071)
    cudaEventRecord(e0, 0);
    cudaStreamWaitEvent(s1, e0, 0);
    qe_mma<<<1024, 128, smem_qe, s1>>>(Qh, rel, QEp);
    cudaEventRecord(e1, s1);
    gemm_mma<<<dim3(16, 32), 256, smem_mm>>>(xhi, xlo, whi, wlo, bq, bk, bv,
                                             nullptr, Qh, Kh, Vh, 1024, 1024, 1024, 1);
    cudaStreamWaitEvent(0, e1, 0);

    flash_mma<<<dim3(64, 16), 128, smem_fl>>>(Qh, Kh, Vh, QEp, aohi, aolo);

    gemm_mma<<<dim3(8, 32), 256, smem_mm>>>(aohi, aolo, whi + 3u * 1024 * 1024, wlo + 3u * 1024 * 1024,
                                            bo, bo, bo, out, nullptr, nullptr, nullptr, 1024, 1024, 0, 0);

    (void)in_sizes; (void)n_in; (void)out_size;
}